// round 9
// baseline (speedup 1.0000x reference)
#include <cuda_runtime.h>
#include <math.h>
#include <stdint.h>

#define N_NODES 100000
#define N_EDGES 1000000
#define DIM     128
#define NH      4
#define NJ      8
#define NK      1000
#define NC      40
#define TOPK    8000            // NJ*NK per head
#define NBINS   65536
#define NCHUNK  256             // 256 chunks x 256 bins
#define CAP     16384
#define NG      32              // NJ*NH
#define NROWS   (NG*NK)         // 32000 msg rows

#define BPSM    3
#define GRID    (148*BPSM)      // 444 blocks, one co-resident wave
#define TPB     512
#define GTH     (GRID*TPB)

// ---------------- scratch: ALL self-cleaning (BSS-zero invariant restored) ----
__device__ int                 d_deg[N_NODES];         // re-zeroed in phase 3
__device__ unsigned            d_hist[NH * NBINS];     // re-zeroed in phase 8
__device__ float               d_acc[N_NODES * NH];    // re-zeroed in phase 3
__device__ unsigned short      d_locmap[N_NODES * NH]; // re-zeroed in phase 9 via sidx
__device__ int                 d_flag[NROWS];          // re-zeroed in phase 9 per-row
__device__ float               d_pooled[NJ * DIM];     // re-zeroed in phase 10
__device__ int                 d_nrows;                // reset in phase 10
__device__ int                 d_rowctr;               // reset in phase 10
__device__ float               d_msg[NROWS * DIM];     // re-zeroed in phase 9 per-row
// ---------------- fully rewritten every run -----------------------------------
__device__ float               d_p[N_NODES * NH];
__device__ float               d_scores[N_NODES * NH];
__device__ unsigned            d_csum[NH * NCHUNK];
__device__ unsigned            d_pref[NH * NBINS];
__device__ int                 d_B[NH];
__device__ int                 d_cnt[NH];
__device__ unsigned long long  d_cbuf[NH * CAP];
__device__ int                 d_sidx[NH * TOPK];
__device__ float               d_vals[NH * TOPK];
__device__ int                 d_rows[NROWS];

// ---------------- hierarchical grid barrier (32 leaves -> root) ---------------
__device__ unsigned g_leaf[32];
__device__ unsigned g_root = 0;
__device__ unsigned g_gen  = 0;

__device__ __forceinline__ unsigned ld_acq(unsigned* p) {
    unsigned v;
    asm volatile("ld.acquire.gpu.global.u32 %0, [%1];" : "=r"(v) : "l"(p) : "memory");
    return v;
}
__device__ __forceinline__ void st_rel(unsigned* p, unsigned v) {
    asm volatile("st.release.gpu.global.u32 [%0], %1;" :: "l"(p), "r"(v) : "memory");
}

__device__ __forceinline__ void gridbar() {
    __syncthreads();
    if (threadIdx.x == 0) {
        unsigned gen = ld_acq(&g_gen);
        __threadfence();                                  // publish block's writes
        int leaf = blockIdx.x & 31;
        unsigned expect = (leaf < 28) ? 14u : 13u;        // 28*14 + 4*13 = 444
        bool released = false;
        if (atomicAdd(&g_leaf[leaf], 1u) == expect - 1u) {
            atomicExch(&g_leaf[leaf], 0u);
            __threadfence();
            if (atomicAdd(&g_root, 1u) == 31u) {
                atomicExch(&g_root, 0u);
                st_rel(&g_gen, gen + 1u);
                released = true;
            }
        }
        if (!released) {
            unsigned ns = 16;
            while (ld_acq(&g_gen) == gen) {
                __nanosleep(ns);
                if (ns < 256) ns += ns;
            }
        }
    }
    __syncthreads();
}

__device__ __forceinline__ unsigned flip_key(float f) {
    unsigned u = __float_as_uint(f);
    return (u >> 31) ? ~u : (u | 0x80000000u);
}

// ================= THE kernel ================================================
__global__ void __launch_bounds__(TPB, BPSM)
K(const float* __restrict__ x, const float* __restrict__ wr,
  const int* __restrict__ ei, const float* __restrict__ ea,
  const float* __restrict__ W1, const float* __restrict__ W2,
  float* __restrict__ out) {
    __shared__ float sbuf[1024];
    __shared__ int   sctl[2];
    const int gtid = blockIdx.x * TPB + threadIdx.x;
    const int t = threadIdx.x;
    const int4* u4p = reinterpret_cast<const int4*>(ei);
    const int4* v4p = reinterpret_cast<const int4*>(ei + N_EDGES);

    // ---- phase 1: in-degree + p = x @ w_rank  (deg is BSS/self-clean zero) ----
    for (int i = gtid; i < N_EDGES / 4; i += GTH) {
        int4 v4 = __ldg(v4p + i);
        atomicAdd(&d_deg[v4.x], 1);
        atomicAdd(&d_deg[v4.y], 1);
        atomicAdd(&d_deg[v4.z], 1);
        atomicAdd(&d_deg[v4.w], 1);
    }
    {
        float* ws = sbuf;                          // w_rank: 512 floats
        ws[t] = __ldg(&wr[t]);                     // TPB == DIM*NH
        __syncthreads();
        for (int n = gtid; n < N_NODES; n += GTH) {
            const float4* xr = reinterpret_cast<const float4*>(x + (size_t)n * DIM);
            float a0 = 0, a1 = 0, a2 = 0, a3 = 0;
            #pragma unroll 4
            for (int c4 = 0; c4 < DIM / 4; c4++) {
                float4 xv = __ldg(&xr[c4]);
                int b = c4 * 16;
                a0 += xv.x * ws[b+0] + xv.y * ws[b+4] + xv.z * ws[b+8]  + xv.w * ws[b+12];
                a1 += xv.x * ws[b+1] + xv.y * ws[b+5] + xv.z * ws[b+9]  + xv.w * ws[b+13];
                a2 += xv.x * ws[b+2] + xv.y * ws[b+6] + xv.z * ws[b+10] + xv.w * ws[b+14];
                a3 += xv.x * ws[b+3] + xv.y * ws[b+7] + xv.z * ws[b+11] + xv.w * ws[b+15];
            }
            *reinterpret_cast<float4*>(&d_p[n * NH]) = make_float4(a0, a1, a2, a3);
        }
    }
    gridbar();

    // ---- phase 2: acc[v] += rsqrt(deg[u])*p[u] ----
    for (int i = gtid; i < N_EDGES / 4; i += GTH) {
        int4 u4 = __ldg(u4p + i);
        int4 v4 = __ldg(v4p + i);
        int us[4] = {u4.x, u4.y, u4.z, u4.w};
        int vs[4] = {v4.x, v4.y, v4.z, v4.w};
        int dg[4]; float4 pp[4];
        #pragma unroll
        for (int s = 0; s < 4; s++) dg[s] = __ldg(&d_deg[us[s]]);
        #pragma unroll
        for (int s = 0; s < 4; s++)
            pp[s] = __ldg(reinterpret_cast<const float4*>(&d_p[us[s] * NH]));
        #pragma unroll
        for (int s = 0; s < 4; s++) {
            float rs = rsqrtf((float)dg[s] + 1.0f);
            asm volatile("red.global.add.v4.f32 [%0], {%1, %2, %3, %4};"
                         :: "l"(&d_acc[vs[s] * NH]),
                            "f"(rs * pp[s].x), "f"(rs * pp[s].y),
                            "f"(rs * pp[s].z), "f"(rs * pp[s].w)
                         : "memory");
        }
    }
    gridbar();

    // ---- phase 3: scores; histogram; self-clean deg + acc ----
    for (int n = gtid; n < N_NODES; n += GTH) {
        float dv  = (float)d_deg[n] + 1.0f;
        float inv = 1.0f / dv;
        float rs  = rsqrtf(dv);
        float4 p4 = *reinterpret_cast<const float4*>(&d_p[n * NH]);
        float4 a4 = *reinterpret_cast<const float4*>(&d_acc[n * NH]);
        float4 s4 = make_float4(p4.x * inv + rs * a4.x, p4.y * inv + rs * a4.y,
                                p4.z * inv + rs * a4.z, p4.w * inv + rs * a4.w);
        *reinterpret_cast<float4*>(&d_scores[n * NH]) = s4;
        d_deg[n] = 0;                                               // self-clean
        *reinterpret_cast<float4*>(&d_acc[n * NH]) = make_float4(0, 0, 0, 0);
        atomicAdd(&d_hist[0 * NBINS + (flip_key(s4.x) >> 16)], 1u);
        atomicAdd(&d_hist[1 * NBINS + (flip_key(s4.y) >> 16)], 1u);
        atomicAdd(&d_hist[2 * NBINS + (flip_key(s4.z) >> 16)], 1u);
        atomicAdd(&d_hist[3 * NBINS + (flip_key(s4.w) >> 16)], 1u);
    }
    gridbar();

    // ---- phase 4: chunk sums (2 jobs per block iter) ----
    {
        unsigned* sh = reinterpret_cast<unsigned*>(sbuf);           // 512
        int half = t >> 8, t2 = t & 255;
        for (int j = blockIdx.x; j < (NH * NCHUNK) / 2; j += GRID) {
            int jj = j * 2 + half;
            int h = jj >> 8, c = jj & 255;
            sh[t] = d_hist[h * NBINS + (NBINS - 1 - (c * 256 + t2))];
            __syncthreads();
            for (int off = 128; off; off >>= 1) {
                if (t2 < off) sh[t] += sh[t + off];
                __syncthreads();
            }
            if (t2 == 0) d_csum[h * NCHUNK + c] = sh[half * 256];
            __syncthreads();
        }
    }
    gridbar();

    // ---- phase 5: chunk prefix + bin prefix + threshold (2 jobs / block iter) ----
    {
        unsigned* sh = reinterpret_cast<unsigned*>(sbuf);           // 512
        unsigned* sb = reinterpret_cast<unsigned*>(sbuf) + 512;     // 512
        int half = t >> 8, t2 = t & 255;
        for (int j = blockIdx.x; j < (NH * NCHUNK) / 2; j += GRID) {
            int jj = j * 2 + half;
            int h = jj >> 8, c = jj & 255;
            sh[t] = d_csum[h * NCHUNK + t2];
            __syncthreads();
            for (int off = 1; off < 256; off <<= 1) {
                unsigned v = (t2 >= off) ? sh[t - off] : 0u;
                __syncthreads();
                sh[t] += v;
                __syncthreads();
            }
            unsigned base = (c > 0) ? sh[half * 256 + c - 1] : 0u;
            int bin = NBINS - 1 - (c * 256 + t2);
            unsigned hv = d_hist[h * NBINS + bin];
            sb[t] = hv;
            __syncthreads();
            for (int off = 1; off < 256; off <<= 1) {
                unsigned v = (t2 >= off) ? sb[t - off] : 0u;
                __syncthreads();
                sb[t] += v;
                __syncthreads();
            }
            unsigned excl = base + sb[t] - hv;
            d_pref[h * NBINS + bin] = excl;
            if (excl < TOPK && excl + hv >= TOPK) {
                d_B[h]   = bin;
                d_cnt[h] = (int)(excl + hv);
            }
            __syncthreads();
        }
    }
    gridbar();

    // ---- phase 6: counting-sort candidates into bin segments ----
    {
        int Bs[4] = {d_B[0], d_B[1], d_B[2], d_B[3]};
        for (int n = gtid; n < N_NODES; n += GTH) {
            float4 s4 = *reinterpret_cast<const float4*>(&d_scores[n * NH]);
            float sv[4] = {s4.x, s4.y, s4.z, s4.w};
            #pragma unroll
            for (int h = 0; h < NH; h++) {
                unsigned key = flip_key(sv[h]);
                int bin = (int)(key >> 16);
                if (bin >= Bs[h]) {
                    unsigned slot = atomicAdd(&d_pref[h * NBINS + bin], 1u);
                    if (slot < CAP)
                        d_cbuf[h * CAP + slot] =
                            ((unsigned long long)key << 32) | (unsigned)(~(unsigned)n);
                }
            }
        }
    }
    gridbar();

    // ---- phase 7: exact rank = bin base + #greater-in-segment ----
    for (int i = gtid; i < NH * CAP; i += GTH) {
        int h = i / CAP, slot = i % CAP;
        if (slot >= d_cnt[h]) continue;
        unsigned long long key = d_cbuf[h * CAP + slot];
        int bin = (int)(key >> 48);
        unsigned segEnd   = d_pref[h * NBINS + bin];   // post-compact = base+occ
        unsigned occ      = d_hist[h * NBINS + bin];
        unsigned segStart = segEnd - occ;
        int rank = (int)segStart;
        for (unsigned j = segStart; j < segEnd; j++)
            if (d_cbuf[h * CAP + j] > key) rank++;
        if (rank < TOPK) {
            unsigned key32 = (unsigned)(key >> 32);
            int n = (int)(~(unsigned)key);
            float f = __uint_as_float((key32 & 0x80000000u) ? (key32 & 0x7FFFFFFFu)
                                                            : ~key32);
            d_sidx[h * TOPK + rank] = n;
            d_vals[h * TOPK + rank] = f;
            d_locmap[n * NH + h] = (unsigned short)(rank + 1);
        }
    }
    gridbar();

    // ---- phase 8: self-clean hist + triples + immediate axpy ----
    {
        uint4* ph = reinterpret_cast<uint4*>(d_hist);
        for (int i = gtid; i < (NH * NBINS) / 4; i += GTH)
            ph[i] = make_uint4(0, 0, 0, 0);
    }
    for (int i = gtid; i < N_EDGES / 4; i += GTH) {
        int4 u4 = __ldg(u4p + i);
        int4 v4 = __ldg(v4p + i);
        int us[4] = {u4.x, u4.y, u4.z, u4.w};
        int vs[4] = {v4.x, v4.y, v4.z, v4.w};
        unsigned long long LU[4], LV[4];
        #pragma unroll
        for (int s = 0; s < 4; s++)
            LU[s] = __ldg(reinterpret_cast<const unsigned long long*>(&d_locmap[us[s] * NH]));
        #pragma unroll
        for (int s = 0; s < 4; s++)
            LV[s] = __ldg(reinterpret_cast<const unsigned long long*>(&d_locmap[vs[s] * NH]));
        #pragma unroll
        for (int s = 0; s < 4; s++) {
            if (LU[s] == 0ull || LV[s] == 0ull) continue;   // fast reject ~92%
            #pragma unroll
            for (int h = 0; h < NH; h++) {
                int lu = (int)((LU[s] >> (16 * h)) & 0xFFFFu);
                int lv = (int)((LV[s] >> (16 * h)) & 0xFFFFu);
                if (lu == 0 || lv == 0) continue;
                int pu = lu - 1, pv = lv - 1;
                int jju = pu / NK;
                if (jju != pv / NK) continue;
                float w = __ldg(&ea[4 * i + s]);
                int g   = jju * NH + h;
                int ku  = pu - jju * NK;
                int kv  = pv - jju * NK;
                int row = g * NK + ku;
                int node = d_sidx[h * TOPK + jju * NK + kv];
                if (atomicExch(&d_flag[row], 1) == 0) {
                    int rp = atomicAdd(&d_nrows, 1);
                    d_rows[rp] = row;
                }
                const float4* xr = reinterpret_cast<const float4*>(x + (size_t)node * DIM);
                float* y = &d_msg[(size_t)row * DIM];
                #pragma unroll 4
                for (int c4 = 0; c4 < DIM / 4; c4++) {
                    float4 xv = __ldg(&xr[c4]);
                    asm volatile("red.global.add.v4.f32 [%0], {%1, %2, %3, %4};"
                                 :: "l"(y + c4 * 4),
                                    "f"(w * xv.x), "f"(w * xv.y), "f"(w * xv.z), "f"(w * xv.w)
                                 : "memory");
                }
            }
        }
    }
    gridbar();

    // ---- phase 9: clear locmap; dynamic rows: gemv + pool + self-clean ----
    for (int i = gtid; i < NH * TOPK; i += GTH) {
        int h = i / TOPK;
        int n = d_sidx[i];
        d_locmap[n * NH + h] = 0;
    }
    {
        float* ys = sbuf;                           // 4 x 128
        int nr = d_nrows;
        int quarter = t >> 7, tl = t & 127;
        for (;;) {
            __syncthreads();
            if (t == 0) sctl[0] = atomicAdd(&d_rowctr, 4);
            __syncthreads();
            int rb = sctl[0];
            if (rb >= nr) break;
            int r = rb + quarter;
            bool active = (r < nr);
            int row = 0;
            if (active) {
                row = d_rows[r];
                ys[quarter * DIM + tl] = d_msg[(size_t)row * DIM + tl];
                d_msg[(size_t)row * DIM + tl] = 0.0f;   // self-clean
                if (tl == 0) d_flag[row] = 0;           // self-clean
            }
            __syncthreads();
            if (active) {
                const float* yrow = &ys[quarter * DIM];
                float acc = 0.0f;
                #pragma unroll 8
                for (int c = 0; c < DIM; c++) acc += yrow[c] * __ldg(&W1[c * DIM + tl]);
                if (acc > 0.0f) {
                    int g = row / NK, ku = row - g * NK;
                    int h = g & 3, jj = g >> 2;
                    float pv = d_vals[h * TOPK + jj * NK + ku];
                    float sg = 1.0f / (1.0f + __expf(-pv));
                    atomicAdd(&d_pooled[jj * DIM + tl], acc * sg);
                }
            }
        }
    }
    gridbar();

    // ---- phase 10: out = log_softmax((pooled/4000) @ W2); reset state (block 0) ----
    if (blockIdx.x == 0) {
        float* lg   = sbuf;          // 320
        float* red2 = sbuf + 336;    // 16
        for (int i = t; i < NJ * NC; i += TPB) {
            int jj = i / NC, c = i - jj * NC;
            float sacc = 0.0f;
            for (int d = 0; d < DIM; d++)
                sacc += d_pooled[jj * DIM + d] * __ldg(&W2[d * NC + c]);
            lg[i] = sacc * (1.0f / 4000.0f);
        }
        __syncthreads();
        // self-clean pooled + counters (all lg reads done)
        for (int i = t; i < NJ * DIM; i += TPB) d_pooled[i] = 0.0f;
        if (t == 0) { d_nrows = 0; d_rowctr = 0; }
        if (t < NJ) {
            float mx = -1e30f;
            for (int c = 0; c < NC; c++) mx = fmaxf(mx, lg[t * NC + c]);
            float se = 0.0f;
            for (int c = 0; c < NC; c++) se += __expf(lg[t * NC + c] - mx);
            red2[t * 2] = mx;
            red2[t * 2 + 1] = __logf(se);
        }
        __syncthreads();
        for (int i = t; i < NJ * NC; i += TPB) {
            int jj = i / NC;
            out[i] = lg[i] - red2[jj * 2] - red2[jj * 2 + 1];
        }
    }
}

// ---------------- host launcher: ONE node ----------------
extern "C" void kernel_launch(void* const* d_in, const int* in_sizes, int n_in,
                              void* d_out, int out_size) {
    const float* x         = (const float*)d_in[0];
    const float* edge_attr = (const float*)d_in[1];
    const float* w_rank    = (const float*)d_in[2];
    const float* W1        = (const float*)d_in[3];
    const float* W2        = (const float*)d_in[4];
    const int*   ei        = (const int*)d_in[5];
    float*       out       = (float*)d_out;

    K<<<GRID, TPB>>>(x, w_rank, ei, edge_attr, W1, W2, out);
}

// round 10
// speedup vs baseline: 1.0802x; 1.0802x over previous
#include <cuda_runtime.h>
#include <math.h>
#include <stdint.h>

#define N_NODES 100000
#define N_EDGES 1000000
#define DIM     128
#define NH      4
#define NJ      8
#define NK      1000
#define NC      40
#define TOPK    8000            // NJ*NK per head
#define NBINS   65536
#define NCHUNK  256             // 256 chunks x 256 bins
#define CAP     16384
#define NG      32              // NJ*NH
#define NROWS   (NG*NK)         // 32000 msg rows
#define NMASKW  ((N_NODES + 7) / 8)

#define BPSM    6
#define GRID    (148*BPSM)      // 888 blocks, one co-resident wave
#define TPB     256
#define GTH     (GRID*TPB)

// ---------------- scratch (all self-cleaning or rewritten every run) ----------
__device__ int                 d_deg[N_NODES];         // zeroed in phase 3
__device__ unsigned            d_hist[NH * NBINS];     // zeroed in phase 1
__device__ float               d_acc[N_NODES * NH];    // zeroed in phase 3
__device__ unsigned short      d_locmap[N_NODES * NH]; // cleared in phase 9 via sidx
__device__ unsigned            d_mask[NMASKW];         // 4-bit presence; cleared phase 9
__device__ int                 d_flag[NROWS];          // cleared per-row phase 9
__device__ float               d_pooled[NJ * DIM];     // zeroed in phase 10
__device__ int                 d_nrows;                // reset in phase 10
__device__ int                 d_rowctr;               // reset in phase 10
__device__ float               d_msg[NROWS * DIM];     // cleared per-row phase 9
__device__ float               d_p[N_NODES * NH];      // p, overwritten by q in 2a
__device__ float               d_scores[N_NODES * NH];
__device__ unsigned            d_csum[NH * NCHUNK];
__device__ unsigned            d_pref[NH * NBINS];
__device__ int                 d_B[NH];
__device__ int                 d_cnt[NH];
__device__ unsigned long long  d_cbuf[NH * CAP];
__device__ int                 d_sidx[NH * TOPK];
__device__ float               d_vals[NH * TOPK];
__device__ int                 d_rows[NROWS];

// ---------------- flat grid barrier (GPU-scope acquire/release) ---------------
__device__ unsigned g_cnt = 0;
__device__ unsigned g_gen = 0;

__device__ __forceinline__ unsigned ld_acq(unsigned* p) {
    unsigned v;
    asm volatile("ld.acquire.gpu.global.u32 %0, [%1];" : "=r"(v) : "l"(p) : "memory");
    return v;
}
__device__ __forceinline__ void st_rel(unsigned* p, unsigned v) {
    asm volatile("st.release.gpu.global.u32 [%0], %1;" :: "l"(p), "r"(v) : "memory");
}

__device__ __forceinline__ void gridbar() {
    __syncthreads();
    if (threadIdx.x == 0) {
        unsigned gen = ld_acq(&g_gen);
        __threadfence();
        if (atomicAdd(&g_cnt, 1u) == (unsigned)(GRID - 1)) {
            g_cnt = 0;
            st_rel(&g_gen, gen + 1u);
        } else {
            unsigned ns = 16;
            while (ld_acq(&g_gen) == gen) {
                __nanosleep(ns);
                if (ns < 256) ns += ns;
            }
        }
    }
    __syncthreads();
}

__device__ __forceinline__ unsigned flip_key(float f) {
    unsigned u = __float_as_uint(f);
    return (u >> 31) ? ~u : (u | 0x80000000u);
}

// ================= THE kernel ================================================
__global__ void __launch_bounds__(TPB, BPSM)
K(const float* __restrict__ x, const float* __restrict__ wr,
  const int* __restrict__ ei, const float* __restrict__ ea,
  const float* __restrict__ W1, const float* __restrict__ W2,
  float* __restrict__ out) {
    __shared__ float sbuf[768];
    __shared__ int   sctl[2];
    const int gtid = blockIdx.x * TPB + threadIdx.x;
    const int t = threadIdx.x;
    const int4* u4p = reinterpret_cast<const int4*>(ei);
    const int4* v4p = reinterpret_cast<const int4*>(ei + N_EDGES);

    // ---- phase 1: zero hist + in-degree RED + p = x @ w_rank ----
    {
        uint4* ph = reinterpret_cast<uint4*>(d_hist);
        for (int i = gtid; i < (NH * NBINS) / 4; i += GTH)
            ph[i] = make_uint4(0, 0, 0, 0);
    }
    for (int i = gtid; i < N_EDGES / 4; i += GTH) {
        int4 v4 = __ldg(v4p + i);
        atomicAdd(&d_deg[v4.x], 1);
        atomicAdd(&d_deg[v4.y], 1);
        atomicAdd(&d_deg[v4.z], 1);
        atomicAdd(&d_deg[v4.w], 1);
    }
    {
        float* ws = sbuf;                          // w_rank: 512 floats
        for (int i = t; i < DIM * NH; i += TPB) ws[i] = __ldg(&wr[i]);
        __syncthreads();
        for (int n = gtid; n < N_NODES; n += GTH) {
            const float4* xr = reinterpret_cast<const float4*>(x + (size_t)n * DIM);
            float a0 = 0, a1 = 0, a2 = 0, a3 = 0;
            #pragma unroll 4
            for (int c4 = 0; c4 < DIM / 4; c4++) {
                float4 xv = __ldg(&xr[c4]);
                int b = c4 * 16;
                a0 += xv.x * ws[b+0] + xv.y * ws[b+4] + xv.z * ws[b+8]  + xv.w * ws[b+12];
                a1 += xv.x * ws[b+1] + xv.y * ws[b+5] + xv.z * ws[b+9]  + xv.w * ws[b+13];
                a2 += xv.x * ws[b+2] + xv.y * ws[b+6] + xv.z * ws[b+10] + xv.w * ws[b+14];
                a3 += xv.x * ws[b+3] + xv.y * ws[b+7] + xv.z * ws[b+11] + xv.w * ws[b+15];
            }
            *reinterpret_cast<float4*>(&d_p[n * NH]) = make_float4(a0, a1, a2, a3);
        }
    }
    gridbar();

    // ---- phase 2a: q = p * rsqrt(deg+1), in place (score = rs*(q+acc)) ----
    for (int n = gtid; n < N_NODES; n += GTH) {
        float rs = rsqrtf((float)d_deg[n] + 1.0f);
        float4 p4 = *reinterpret_cast<const float4*>(&d_p[n * NH]);
        *reinterpret_cast<float4*>(&d_p[n * NH]) =
            make_float4(p4.x * rs, p4.y * rs, p4.z * rs, p4.w * rs);
    }
    gridbar();

    // ---- phase 2b: acc[v] += q[u]  (single 16B gather + 16B red per edge) ----
    for (int i = gtid; i < N_EDGES / 4; i += GTH) {
        int4 u4 = __ldg(u4p + i);
        int4 v4 = __ldg(v4p + i);
        int us[4] = {u4.x, u4.y, u4.z, u4.w};
        int vs[4] = {v4.x, v4.y, v4.z, v4.w};
        float4 qq[4];
        #pragma unroll
        for (int s = 0; s < 4; s++)
            qq[s] = __ldg(reinterpret_cast<const float4*>(&d_p[us[s] * NH]));
        #pragma unroll
        for (int s = 0; s < 4; s++) {
            asm volatile("red.global.add.v4.f32 [%0], {%1, %2, %3, %4};"
                         :: "l"(&d_acc[vs[s] * NH]),
                            "f"(qq[s].x), "f"(qq[s].y), "f"(qq[s].z), "f"(qq[s].w)
                         : "memory");
        }
    }
    gridbar();

    // ---- phase 3: scores = rs*(q+acc); histogram; self-clean deg + acc ----
    for (int n = gtid; n < N_NODES; n += GTH) {
        float rs  = rsqrtf((float)d_deg[n] + 1.0f);
        float4 q4 = *reinterpret_cast<const float4*>(&d_p[n * NH]);
        float4 a4 = *reinterpret_cast<const float4*>(&d_acc[n * NH]);
        float4 s4 = make_float4(rs * (q4.x + a4.x), rs * (q4.y + a4.y),
                                rs * (q4.z + a4.z), rs * (q4.w + a4.w));
        *reinterpret_cast<float4*>(&d_scores[n * NH]) = s4;
        d_deg[n] = 0;                                               // self-clean
        *reinterpret_cast<float4*>(&d_acc[n * NH]) = make_float4(0, 0, 0, 0);
        atomicAdd(&d_hist[0 * NBINS + (flip_key(s4.x) >> 16)], 1u);
        atomicAdd(&d_hist[1 * NBINS + (flip_key(s4.y) >> 16)], 1u);
        atomicAdd(&d_hist[2 * NBINS + (flip_key(s4.z) >> 16)], 1u);
        atomicAdd(&d_hist[3 * NBINS + (flip_key(s4.w) >> 16)], 1u);
    }
    gridbar();

    // ---- phase 4: chunk sums (1024 coalesced jobs) ----
    {
        unsigned* sh = reinterpret_cast<unsigned*>(sbuf);
        for (int j = blockIdx.x; j < NH * NCHUNK; j += GRID) {
            int h = j >> 8, c = j & 255;
            sh[t] = d_hist[h * NBINS + (NBINS - 1 - (c * 256 + t))];
            __syncthreads();
            for (int off = 128; off; off >>= 1) {
                if (t < off) sh[t] += sh[t + off];
                __syncthreads();
            }
            if (t == 0) d_csum[h * NCHUNK + c] = sh[0];
            __syncthreads();
        }
    }
    gridbar();

    // ---- phase 5: chunk prefix + bin prefix + threshold (1024 jobs) ----
    {
        unsigned* sh = reinterpret_cast<unsigned*>(sbuf);
        unsigned* sb = reinterpret_cast<unsigned*>(sbuf) + 256;
        for (int j = blockIdx.x; j < NH * NCHUNK; j += GRID) {
            int h = j >> 8, c = j & 255;
            sh[t] = d_csum[h * NCHUNK + t];
            __syncthreads();
            for (int off = 1; off < 256; off <<= 1) {
                unsigned v = (t >= off) ? sh[t - off] : 0u;
                __syncthreads();
                sh[t] += v;
                __syncthreads();
            }
            unsigned base = (c > 0) ? sh[c - 1] : 0u;
            int bin = NBINS - 1 - (c * 256 + t);
            unsigned hv = d_hist[h * NBINS + bin];
            sb[t] = hv;
            __syncthreads();
            for (int off = 1; off < 256; off <<= 1) {
                unsigned v = (t >= off) ? sb[t - off] : 0u;
                __syncthreads();
                sb[t] += v;
                __syncthreads();
            }
            unsigned excl = base + sb[t] - hv;
            d_pref[h * NBINS + bin] = excl;
            if (excl < TOPK && excl + hv >= TOPK) {
                d_B[h]   = bin;
                d_cnt[h] = (int)(excl + hv);
            }
            __syncthreads();
        }
    }
    gridbar();

    // ---- phase 6: counting-sort candidates into bin segments ----
    {
        int Bs[4] = {d_B[0], d_B[1], d_B[2], d_B[3]};
        for (int n = gtid; n < N_NODES; n += GTH) {
            float4 s4 = *reinterpret_cast<const float4*>(&d_scores[n * NH]);
            float sv[4] = {s4.x, s4.y, s4.z, s4.w};
            #pragma unroll
            for (int h = 0; h < NH; h++) {
                unsigned key = flip_key(sv[h]);
                int bin = (int)(key >> 16);
                if (bin >= Bs[h]) {
                    unsigned slot = atomicAdd(&d_pref[h * NBINS + bin], 1u);
                    if (slot < CAP)
                        d_cbuf[h * CAP + slot] =
                            ((unsigned long long)key << 32) | (unsigned)(~(unsigned)n);
                }
            }
        }
    }
    gridbar();

    // ---- phase 7: exact rank; emit sidx/vals/locmap + presence nibble ----
    for (int i = gtid; i < NH * CAP; i += GTH) {
        int h = i / CAP, slot = i % CAP;
        if (slot >= d_cnt[h]) continue;
        unsigned long long key = d_cbuf[h * CAP + slot];
        int bin = (int)(key >> 48);
        unsigned segEnd   = d_pref[h * NBINS + bin];   // post-compact = base+occ
        unsigned occ      = d_hist[h * NBINS + bin];
        unsigned segStart = segEnd - occ;
        int rank = (int)segStart;
        for (unsigned j = segStart; j < segEnd; j++)
            if (d_cbuf[h * CAP + j] > key) rank++;
        if (rank < TOPK) {
            unsigned key32 = (unsigned)(key >> 32);
            int n = (int)(~(unsigned)key);
            float f = __uint_as_float((key32 & 0x80000000u) ? (key32 & 0x7FFFFFFFu)
                                                            : ~key32);
            d_sidx[h * TOPK + rank] = n;
            d_vals[h * TOPK + rank] = f;
            d_locmap[n * NH + h] = (unsigned short)(rank + 1);
            atomicOr(&d_mask[n >> 3], (1u << h) << ((n & 7) * 4));
        }
    }
    gridbar();

    // ---- phase 8: nibble-gated triples + immediate axpy y[row] += w*x[node] ----
    for (int i = gtid; i < N_EDGES / 4; i += GTH) {
        int4 u4 = __ldg(u4p + i);
        int us[4] = {u4.x, u4.y, u4.z, u4.w};
        unsigned mu[4];
        #pragma unroll
        for (int s = 0; s < 4; s++)
            mu[s] = (__ldg(&d_mask[us[s] >> 3]) >> ((us[s] & 7) * 4)) & 0xFu;
        if (!(mu[0] | mu[1] | mu[2] | mu[3])) continue;
        int4 v4 = __ldg(v4p + i);
        int vs[4] = {v4.x, v4.y, v4.z, v4.w};
        #pragma unroll
        for (int s = 0; s < 4; s++) {
            if (!mu[s]) continue;
            unsigned mv = (__ldg(&d_mask[vs[s] >> 3]) >> ((vs[s] & 7) * 4)) & 0xFu;
            unsigned mm = mu[s] & mv;
            if (!mm) continue;                     // survives ~2.5% of edges
            unsigned long long LU =
                __ldg(reinterpret_cast<const unsigned long long*>(&d_locmap[us[s] * NH]));
            unsigned long long LV =
                __ldg(reinterpret_cast<const unsigned long long*>(&d_locmap[vs[s] * NH]));
            #pragma unroll
            for (int h = 0; h < NH; h++) {
                if (!((mm >> h) & 1u)) continue;
                int pu = (int)((LU >> (16 * h)) & 0xFFFFu) - 1;
                int pv = (int)((LV >> (16 * h)) & 0xFFFFu) - 1;
                int jju = pu / NK;
                if (jju != pv / NK) continue;
                float w = __ldg(&ea[4 * i + s]);
                int g   = jju * NH + h;
                int ku  = pu - jju * NK;
                int kv  = pv - jju * NK;
                int row = g * NK + ku;
                int node = d_sidx[h * TOPK + jju * NK + kv];
                if (atomicExch(&d_flag[row], 1) == 0) {
                    int rp = atomicAdd(&d_nrows, 1);
                    d_rows[rp] = row;
                }
                const float4* xr = reinterpret_cast<const float4*>(x + (size_t)node * DIM);
                float* y = &d_msg[(size_t)row * DIM];
                #pragma unroll 4
                for (int c4 = 0; c4 < DIM / 4; c4++) {
                    float4 xv = __ldg(&xr[c4]);
                    asm volatile("red.global.add.v4.f32 [%0], {%1, %2, %3, %4};"
                                 :: "l"(y + c4 * 4),
                                    "f"(w * xv.x), "f"(w * xv.y), "f"(w * xv.z), "f"(w * xv.w)
                                 : "memory");
                }
            }
        }
    }
    gridbar();

    // ---- phase 9: clear locmap+mask; dynamic rows: gemv + pool + self-clean ----
    for (int i = gtid; i < NH * TOPK; i += GTH) {
        int h = i / TOPK;
        int n = d_sidx[i];
        d_locmap[n * NH + h] = 0;
    }
    for (int i = gtid; i < NMASKW; i += GTH) d_mask[i] = 0u;
    {
        float* ys = sbuf;                           // 2 x 128
        int nr = d_nrows;
        int half = t >> 7, tl = t & 127;
        for (;;) {
            __syncthreads();
            if (t == 0) sctl[0] = atomicAdd(&d_rowctr, 2);
            __syncthreads();
            int rb = sctl[0];
            if (rb >= nr) break;
            int r = rb + half;
            bool active = (r < nr);
            int row = 0;
            if (active) {
                row = d_rows[r];
                ys[half * DIM + tl] = d_msg[(size_t)row * DIM + tl];
                d_msg[(size_t)row * DIM + tl] = 0.0f;   // self-clean
                if (tl == 0) d_flag[row] = 0;           // self-clean
            }
            __syncthreads();
            if (active) {
                const float* yrow = &ys[half * DIM];
                float acc = 0.0f;
                #pragma unroll 8
                for (int c = 0; c < DIM; c++) acc += yrow[c] * __ldg(&W1[c * DIM + tl]);
                if (acc > 0.0f) {
                    int g = row / NK, ku = row - g * NK;
                    int h = g & 3, jj = g >> 2;
                    float pv = d_vals[h * TOPK + jj * NK + ku];
                    float sg = 1.0f / (1.0f + __expf(-pv));
                    atomicAdd(&d_pooled[jj * DIM + tl], acc * sg);
                }
            }
        }
    }
    gridbar();

    // ---- phase 10: out = log_softmax((pooled/4000) @ W2); reset state (block 0) ----
    if (blockIdx.x == 0) {
        float* lg   = sbuf;          // 320
        float* red2 = sbuf + 336;    // 16
        for (int i = t; i < NJ * NC; i += TPB) {
            int jj = i / NC, c = i - jj * NC;
            float sacc = 0.0f;
            for (int d = 0; d < DIM; d++)
                sacc += d_pooled[jj * DIM + d] * __ldg(&W2[d * NC + c]);
            lg[i] = sacc * (1.0f / 4000.0f);
        }
        __syncthreads();
        for (int i = t; i < NJ * DIM; i += TPB) d_pooled[i] = 0.0f;  // self-clean
        if (t == 0) { d_nrows = 0; d_rowctr = 0; }
        if (t < NJ) {
            float mx = -1e30f;
            for (int c = 0; c < NC; c++) mx = fmaxf(mx, lg[t * NC + c]);
            float se = 0.0f;
            for (int c = 0; c < NC; c++) se += __expf(lg[t * NC + c] - mx);
            red2[t * 2] = mx;
            red2[t * 2 + 1] = __logf(se);
        }
        __syncthreads();
        for (int i = t; i < NJ * NC; i += TPB) {
            int jj = i / NC;
            out[i] = lg[i] - red2[jj * 2] - red2[jj * 2 + 1];
        }
    }
}

// ---------------- host launcher: ONE node ----------------
extern "C" void kernel_launch(void* const* d_in, const int* in_sizes, int n_in,
                              void* d_out, int out_size) {
    const float* x         = (const float*)d_in[0];
    const float* edge_attr = (const float*)d_in[1];
    const float* w_rank    = (const float*)d_in[2];
    const float* W1        = (const float*)d_in[3];
    const float* W2        = (const float*)d_in[4];
    const int*   ei        = (const int*)d_in[5];
    float*       out       = (float*)d_out;

    K<<<GRID, TPB>>>(x, w_rank, ei, edge_attr, W1, W2, out);
}